// round 12
// baseline (speedup 1.0000x reference)
#include <cuda_runtime.h>

#define BB 256
#define NN 192
#define CC 256
#define GG 8
#define DD 32

// softmax via exp2: fold SCALE * log2(e) into q-tilde
#define CSCALE (0.17677669529663688f * 1.4426950408889634f)

typedef unsigned long long u64;

// scratch (allocation-free rule: __device__ global)
// g_qt[b][n][g*32+i2] = CSCALE * (Wk_g^T (x_n Wq^T + bq))[i2]
__device__ float g_qt[BB * NN * CC];            // 50 MB
// fallback p buffer only if harness doesn't want attn output
__device__ float g_ps[(size_t)BB * GG * NN * NN];  // 302 MB (bss, unused normally)

// ---------- packed f32x2 helpers (sm_100+) ----------
__device__ __forceinline__ u64 pack2(float x, float y) {
    u64 r; asm("mov.b64 %0,{%1,%2};" : "=l"(r) : "f"(x), "f"(y)); return r;
}
__device__ __forceinline__ void unpack2(u64 v, float& x, float& y) {
    asm("mov.b64 {%0,%1},%2;" : "=f"(x), "=f"(y) : "l"(v));
}
__device__ __forceinline__ void ffma2(u64& d, u64 a, u64 b) {
    asm("fma.rn.f32x2 %0,%1,%2,%0;" : "+l"(d) : "l"(a), "l"(b));
}
__device__ __forceinline__ float ex2(float x) {
    float r; asm("ex2.approx.ftz.f32 %0,%1;" : "=f"(r) : "f"(x)); return r;
}

// ============================================================
// proj_qt: UNCHANGED (known-good).
// bk is provably irrelevant (constant-in-j logit shift, cancels in softmax).
// ============================================================
__global__ void __launch_bounds__(128, 3) proj_qt_kernel(
    const float* __restrict__ x, const float* __restrict__ Wq,
    const float* __restrict__ bq, const float* __restrict__ Wk)
{
    extern __shared__ u64 smq[];
    u64* xs2 = smq;            // [32][128] u64 = 32KB (phase A)
    u64* Wt2 = smq + 4096;     // [128][32] u64 = 32KB (phase A)
    float* qs = (float*)smq;   // [32][34] floats (phase B, aliases xs2)
    u64* Wk2  = smq + 4096;    // [8][16][32] u64 = 32KB (phase B, aliases Wt2)

    const int tid = threadIdx.x;
    const int w = tid >> 5, lane = tid & 31;
    const long row0 = (long)blockIdx.x * 32;

    for (int idx = tid; idx < DD * CC; idx += 128) {
        int d = idx >> 8, c = idx & 255;
        ((float*)&Wt2[(c >> 1) * 32 + d])[c & 1] = Wq[idx];
    }
    {
        const float4* src = (const float4*)(x + row0 * CC);
        float4* dst = (float4*)xs2;
#pragma unroll
        for (int t = 0; t < 16; ++t) dst[tid + t * 128] = src[tid + t * 128];
    }
    __syncthreads();

    float qv[8];
    {
        u64 acc[8];
#pragma unroll
        for (int r = 0; r < 8; ++r) acc[r] = 0ull;
        const u64* xbase = xs2 + (w * 8) * 128;
#pragma unroll 4
        for (int c2 = 0; c2 < 128; ++c2) {
            u64 w2 = Wt2[c2 * 32 + lane];
#pragma unroll
            for (int r = 0; r < 8; ++r)
                ffma2(acc[r], xbase[r * 128 + c2], w2);
        }
        const float bias = bq[lane];
#pragma unroll
        for (int r = 0; r < 8; ++r) {
            float lo, hi; unpack2(acc[r], lo, hi);
            qv[r] = (lo + hi + bias) * CSCALE;
        }
    }
    __syncthreads();

#pragma unroll
    for (int r = 0; r < 8; ++r) qs[(w * 8 + r) * 34 + lane] = qv[r];
    for (int idx = tid; idx < GG * 16 * 32; idx += 128) {
        int g = idx >> 9, o2 = (idx >> 5) & 15, i2 = idx & 31;
        Wk2[idx] = pack2(Wk[(g * 32 + 2 * o2) * 32 + i2],
                         Wk[(g * 32 + 2 * o2 + 1) * 32 + i2]);
    }
    __syncthreads();

    {
        const int c0 = tid, c1 = tid + 128;
        const u64* wk0 = Wk2 + (c0 >> 5) * 512 + (c0 & 31);
        const u64* wk1 = Wk2 + (c1 >> 5) * 512 + (c1 & 31);
        const u64* qs2 = (const u64*)qs;   // row stride 17 u64
#pragma unroll 1
        for (int ch = 0; ch < 4; ++ch) {
            u64 a0[8], a1[8];
#pragma unroll
            for (int r = 0; r < 8; ++r) { a0[r] = 0ull; a1[r] = 0ull; }
#pragma unroll
            for (int o2 = 0; o2 < 16; ++o2) {
                u64 w0 = wk0[o2 * 32], w1 = wk1[o2 * 32];
#pragma unroll
                for (int r = 0; r < 8; ++r) {
                    u64 q2 = qs2[(ch * 8 + r) * 17 + o2];  // broadcast
                    ffma2(a0[r], q2, w0);
                    ffma2(a1[r], q2, w1);
                }
            }
#pragma unroll
            for (int r = 0; r < 8; ++r) {
                float l0, h0, l1, h1;
                unpack2(a0[r], l0, h0); unpack2(a1[r], l1, h1);
                const long row = row0 + ch * 8 + r;
                g_qt[row * CC + c0] = l0 + h0;
                g_qt[row * CC + c1] = l1 + h1;
            }
        }
    }
}

// ============================================================
// p-kernel: S = qt x^T + fused softmax; writes normalized p ONLY to gmem
// (p_buf = attn output, which doubles as staging for the ctx kernel).
// 1 block per (b,g,i-half of 96); 384 threads; smem 38.9KB; 24 warps/SM.
//   q_s [96][36]  @ 0     (3456 floats)
//   vT  [32][196] @ 3456  (6272 floats)
// Tile: 4i x 12j per thread (iq = tid>>4 in 0..23, jq = tid&15).
// No max subtraction (|S_log2| <~ 13, exp2 safe in fp32; softmax is
// shift-invariant so result identical). Row sums via half-warp shfl.
// ============================================================
#define OFF_VT  3456
#define SMP_FLOATS 9728

__global__ void __launch_bounds__(384, 2) p_kernel(
    const float* __restrict__ x, float* __restrict__ p_buf)
{
    extern __shared__ float sm[];
    float* q_s = sm;
    float* vT  = sm + OFF_VT;

    const int tid = threadIdx.x;
    const int bg = blockIdx.x >> 1;        // b*8+g
    const int b = bg >> 3, g = bg & 7;
    const int i0 = (blockIdx.x & 1) * 96;

    // ---------------- P0: stage q_s (row-major) and vT (transposed) ------
#pragma unroll
    for (int t = 0; t < 2; ++t) {          // 96 rows x 8 float4 = 768
        int idx = tid + t * 384;
        int i = idx >> 3, f = idx & 7;
        ((float4*)(q_s + i * 36))[f] =
            ((const float4*)(g_qt + ((size_t)(b * NN) + i0 + i) * CC + g * DD))[f];
    }
#pragma unroll
    for (int t = 0; t < 4; ++t) {          // 1536 float4, transpose scatter
        int idx = tid + t * 384;
        int n = idx >> 3, f = idx & 7;
        float4 v4 = ((const float4*)(x + ((size_t)(b * NN) + n) * CC + g * DD))[f];
        vT[(4 * f    ) * 196 + n] = v4.x;
        vT[(4 * f + 1) * 196 + n] = v4.y;
        vT[(4 * f + 2) * 196 + n] = v4.z;
        vT[(4 * f + 3) * 196 + n] = v4.w;
    }
    __syncthreads();

    // ---------------- P1: S + fused softmax + p write --------------------
    // jq -> j block [12jq, 12jq+12); iq -> i = iq + 24m, m<4
    const int jq = tid & 15, iq = tid >> 4;
    u64 acc[24];
#pragma unroll
    for (int t = 0; t < 24; ++t) acc[t] = 0ull;

#pragma unroll 1
    for (int d2 = 0; d2 < 16; ++d2) {
        const int d0 = 2 * d2;
        u64 qp[4];
#pragma unroll
        for (int m = 0; m < 4; ++m)
            qp[m] = *(const u64*)(q_s + (iq + 24 * m) * 36 + d0);  // (d0,d0+1)
        {   // v row d0
            const float4* vr = (const float4*)(vT + d0 * 196);
            u64 vv[6];
#pragma unroll
            for (int c = 0; c < 3; ++c) {
                float4 v4 = vr[3 * jq + c];
                vv[2 * c]     = pack2(v4.x, v4.y);
                vv[2 * c + 1] = pack2(v4.z, v4.w);
            }
#pragma unroll
            for (int m = 0; m < 4; ++m) {
                float ql, qh; unpack2(qp[m], ql, qh); (void)qh;
                u64 qa = pack2(ql, ql);
#pragma unroll
                for (int n = 0; n < 6; ++n)
                    ffma2(acc[m * 6 + n], qa, vv[n]);
            }
        }
        {   // v row d0+1
            const float4* vr = (const float4*)(vT + (d0 + 1) * 196);
            u64 vv[6];
#pragma unroll
            for (int c = 0; c < 3; ++c) {
                float4 v4 = vr[3 * jq + c];
                vv[2 * c]     = pack2(v4.x, v4.y);
                vv[2 * c + 1] = pack2(v4.z, v4.w);
            }
#pragma unroll
            for (int m = 0; m < 4; ++m) {
                float ql, qh; unpack2(qp[m], ql, qh); (void)ql;
                u64 qb = pack2(qh, qh);
#pragma unroll
                for (int n = 0; n < 6; ++n)
                    ffma2(acc[m * 6 + n], qb, vv[n]);
            }
        }
    }

    // ---- fused softmax epilogue (registers + half-warp shfl) ----
    float e[48];
#pragma unroll
    for (int t = 0; t < 24; ++t) {
        float lo, hi; unpack2(acc[t], lo, hi);
        e[2 * t]     = ex2(lo);
        e[2 * t + 1] = ex2(hi);
    }
    float inv[4];
#pragma unroll
    for (int m = 0; m < 4; ++m) {
        float s = 0.f;
#pragma unroll
        for (int jj = 0; jj < 12; ++jj) s += e[m * 12 + jj];
        // 16 lanes sharing iq are a contiguous half-warp covering all j
#pragma unroll
        for (int o = 1; o < 16; o <<= 1)
            s += __shfl_xor_sync(0xffffffffu, s, o);
        inv[m] = 1.0f / s;
    }
    // normalized p straight to gmem (coalesced STG.128)
#pragma unroll
    for (int m = 0; m < 4; ++m) {
        const int i = iq + 24 * m;
        float4* adst = (float4*)(p_buf +
            ((size_t)bg * NN + i0 + i) * NN + 12 * jq);
#pragma unroll
        for (int c = 0; c < 3; ++c)
            adst[c] = make_float4(e[m * 12 + 4 * c    ] * inv[m],
                                  e[m * 12 + 4 * c + 1] * inv[m],
                                  e[m * 12 + 4 * c + 2] * inv[m],
                                  e[m * 12 + 4 * c + 3] * inv[m]);
    }
}

// ============================================================
// ctx-kernel: ctx[b,i,g,d] = sum_j p[bg,i,j] * v[b,j,g,d]
// 1 block per (b,g); 256 threads; smem = vT 25,088B; occ 3 (24 warps).
// Tile: 6i x 4d per thread (ig = tid>>3 in 0..31, dg = tid&7).
// p streamed from gmem (LDG.128), v from smem, pairs along j.
// ============================================================
__global__ void __launch_bounds__(256, 3) ctx_kernel(
    const float* __restrict__ x, const float* __restrict__ p_buf,
    float* __restrict__ ctx_out)
{
    extern __shared__ float sm[];
    float* vT = sm;                        // [32][196]

    const int tid = threadIdx.x;
    const int bg = blockIdx.x;             // b*8+g
    const int b = bg >> 3, g = bg & 7;

    // stage vT (transposed x group slice)
#pragma unroll
    for (int t = 0; t < 6; ++t) {          // 1536 float4
        int idx = tid + t * 256;
        int n = idx >> 3, f = idx & 7;
        float4 v4 = ((const float4*)(x + ((size_t)(b * NN) + n) * CC + g * DD))[f];
        vT[(4 * f    ) * 196 + n] = v4.x;
        vT[(4 * f + 1) * 196 + n] = v4.y;
        vT[(4 * f + 2) * 196 + n] = v4.z;
        vT[(4 * f + 3) * 196 + n] = v4.w;
    }
    __syncthreads();

    const int dg = tid & 7, ig = tid >> 3;
    const float* prow0 = p_buf + (size_t)bg * NN * NN + (size_t)(6 * ig) * NN;

    u64 acc[24];
#pragma unroll
    for (int t = 0; t < 24; ++t) acc[t] = 0ull;

#pragma unroll 1
    for (int c = 0; c < 48; ++c) {         // 4 j per step
        u64 v2[8];
#pragma unroll
        for (int dd = 0; dd < 4; ++dd) {
            float4 v4 = ((const float4*)(vT + (4 * dg + dd) * 196))[c];
            v2[2 * dd]     = pack2(v4.x, v4.y);
            v2[2 * dd + 1] = pack2(v4.z, v4.w);
        }
#pragma unroll
        for (int a = 0; a < 6; ++a) {
            float4 p4 = ((const float4*)(prow0 + a * NN))[c];
            u64 p0 = pack2(p4.x, p4.y), p1 = pack2(p4.z, p4.w);
#pragma unroll
            for (int dd = 0; dd < 4; ++dd) {
                ffma2(acc[a * 4 + dd], p0, v2[2 * dd]);
                ffma2(acc[a * 4 + dd], p1, v2[2 * dd + 1]);
            }
        }
    }
#pragma unroll
    for (int a = 0; a < 6; ++a) {
        const size_t row = (size_t)(b * NN) + 6 * ig + a;
        float o[4];
#pragma unroll
        for (int dd = 0; dd < 4; ++dd) {
            float lo, hi; unpack2(acc[a * 4 + dd], lo, hi);
            o[dd] = lo + hi;
        }
        *(float4*)(ctx_out + row * CC + g * DD + 4 * dg) =
            make_float4(o[0], o[1], o[2], o[3]);
    }
}

extern "C" void kernel_launch(void* const* d_in, const int* in_sizes, int n_in,
                              void* d_out, int out_size)
{
    const float* x  = (const float*)d_in[0];
    const float* Wq = (const float*)d_in[1];
    const float* bq = (const float*)d_in[2];
    const float* Wk = (const float*)d_in[3];
    // d_in[4] = bk: provably no effect on outputs (cancels in softmax)

    const size_t ctx_elems  = (size_t)BB * NN * CC;          // 12,582,912
    const size_t attn_elems = (size_t)BB * GG * NN * NN;     // 75,497,472

    float* ctx_ptr  = nullptr;
    float* attn_ptr = nullptr;
    const size_t osz = (size_t)out_size;
    if (osz >= ctx_elems + attn_elems) {          // tuple flattened: ctx then attn
        ctx_ptr  = (float*)d_out;
        attn_ptr = (float*)d_out + ctx_elems;
    } else if (osz == attn_elems) {               // attn only
        attn_ptr = (float*)d_out;
    } else {                                      // ctx only
        ctx_ptr = (float*)d_out;
    }

    // p always needs a home: attn output if present, else scratch
    float* p_buf = attn_ptr;
    if (!p_buf) {
        cudaError_t e = cudaGetSymbolAddress((void**)&p_buf, g_ps);
        (void)e;
    }

    constexpr int SMEM_P  = 64 * 1024;            // proj: 65536 -> occ 3
    constexpr int SMEM_PK = SMP_FLOATS * 4;       // p-kernel: 38912
    constexpr int SMEM_CK = 32 * 196 * 4;         // ctx: 25088 -> occ 3
    cudaFuncSetAttribute(proj_qt_kernel, cudaFuncAttributeMaxDynamicSharedMemorySize, SMEM_P);
    cudaFuncSetAttribute(p_kernel,       cudaFuncAttributeMaxDynamicSharedMemorySize, SMEM_PK);
    cudaFuncSetAttribute(ctx_kernel,     cudaFuncAttributeMaxDynamicSharedMemorySize, SMEM_CK);

    proj_qt_kernel<<<BB * NN / 32, 128, SMEM_P>>>(x, Wq, bq, Wk);
    p_kernel<<<BB * GG * 2, 384, SMEM_PK>>>(x, p_buf);
    if (ctx_ptr)
        ctx_kernel<<<BB * GG, 256, SMEM_CK>>>(x, p_buf, ctx_ptr);
}

// round 13
// speedup vs baseline: 1.3573x; 1.3573x over previous
#include <cuda_runtime.h>

#define BB 256
#define NN 192
#define CC 256
#define GG 8
#define DD 32

// softmax via exp2: fold SCALE * log2(e) into q
#define CSCALE (0.17677669529663688f * 1.4426950408889634f)

typedef unsigned long long u64;

// scratch (allocation-free rule: __device__ global)
// g_q[b][n][o] = CSCALE * (x_n Wq^T + bq)[o]   (6 MB)
__device__ float g_q[BB * NN * DD];

// ---------- packed f32x2 helpers (sm_100+) ----------
__device__ __forceinline__ u64 pack2(float x, float y) {
    u64 r; asm("mov.b64 %0,{%1,%2};" : "=l"(r) : "f"(x), "f"(y)); return r;
}
__device__ __forceinline__ void unpack2(u64 v, float& x, float& y) {
    asm("mov.b64 {%0,%1},%2;" : "=f"(x), "=f"(y) : "l"(v));
}
__device__ __forceinline__ void ffma2(u64& d, u64 a, u64 b) {
    asm("fma.rn.f32x2 %0,%1,%2,%0;" : "+l"(d) : "l"(a), "l"(b));
}
__device__ __forceinline__ float ex2(float x) {
    float r; asm("ex2.approx.ftz.f32 %0,%1;" : "=f"(r) : "f"(x)); return r;
}

// ============================================================
// proj_q: q = (x Wq^T + bq) * CSCALE  (phase A of old proj_qt; phase B
// is now fused into attn). 32 rows/block, 128 threads, 64KB smem, occ 3.
// bk is provably irrelevant (constant-in-j logit shift, cancels in softmax).
// ============================================================
__global__ void __launch_bounds__(128, 3) proj_q_kernel(
    const float* __restrict__ x, const float* __restrict__ Wq,
    const float* __restrict__ bq)
{
    extern __shared__ u64 smq[];
    u64* xs2 = smq;            // [32][128] u64 = 32KB
    u64* Wt2 = smq + 4096;     // [128][32] u64 = 32KB

    const int tid = threadIdx.x;
    const int w = tid >> 5, lane = tid & 31;
    const long row0 = (long)blockIdx.x * 32;

    for (int idx = tid; idx < DD * CC; idx += 128) {
        int d = idx >> 8, c = idx & 255;
        ((float*)&Wt2[(c >> 1) * 32 + d])[c & 1] = Wq[idx];
    }
    {
        const float4* src = (const float4*)(x + row0 * CC);
        float4* dst = (float4*)xs2;
#pragma unroll
        for (int t = 0; t < 16; ++t) dst[tid + t * 128] = src[tid + t * 128];
    }
    __syncthreads();

    u64 acc[8];
#pragma unroll
    for (int r = 0; r < 8; ++r) acc[r] = 0ull;
    const u64* xbase = xs2 + (w * 8) * 128;
#pragma unroll 4
    for (int c2 = 0; c2 < 128; ++c2) {
        u64 w2 = Wt2[c2 * 32 + lane];
#pragma unroll
        for (int r = 0; r < 8; ++r)
            ffma2(acc[r], xbase[r * 128 + c2], w2);
    }
    const float bias = bq[lane];
#pragma unroll
    for (int r = 0; r < 8; ++r) {
        float lo, hi; unpack2(acc[r], lo, hi);
        g_q[(row0 + w * 8 + r) * DD + lane] = (lo + hi + bias) * CSCALE;
    }
}

// ============================================================
// attn: 1 block per (b,g,i-half of 96); 384 threads; 114,176B smem;
// occ 2 -> 24 warps/SM.
//   q_s [96][36]  @ 0     (3456 floats)  qt rows (computed in P0b)
//   vT  [32][196] @ 3456  (6272 floats)  x group slice transposed [d][j]
//   ST  [96][196] @ 9728  (18816 floats) P0: rawq[96][36]+Wk2[512]; P1+: p
// P0 : stage rawq (from g_q), Wk_g, vT
// P0b: qt[i][i2] = sum_o rawq[i][o] * Wk[g][o][i2]  -> q_s (98K MACs, cheap)
// P1 : S = qt vT (tile 4i x 12j) + fused no-max softmax (half-warp shfl)
//      -> normalized p to ST + attn gmem, straight from registers
// P3 : ctx = P V (tile 4i x 2d, e-row broadcast, float4 j-steps)
// ============================================================
#define OFF_VT  3456
#define OFF_ST  9728
#define SM_FLOATS 28544

__global__ void __launch_bounds__(384, 2) attn_kernel(
    const float* __restrict__ x, const float* __restrict__ Wk,
    float* __restrict__ ctx_out, float* __restrict__ attn_out)
{
    extern __shared__ float sm[];
    float* q_s  = sm;
    float* vT   = sm + OFF_VT;
    float* ST   = sm + OFF_ST;
    float* rawq = ST;                     // [96][36], P0 only (dead after P0b)
    u64*   Wk2  = (u64*)(ST + 3456);      // [512] = Wk[g] as (even,odd) pairs

    const int tid = threadIdx.x;
    const int bg = blockIdx.x >> 1;        // b*8+g
    const int b = bg >> 3, g = bg & 7;
    const int i0 = (blockIdx.x & 1) * 96;

    // ---------------- P0: stage rawq, Wk2, vT ----------------------------
#pragma unroll
    for (int t = 0; t < 2; ++t) {          // 96 rows x 8 float4 = 768
        int idx = tid + t * 384;
        int i = idx >> 3, f = idx & 7;
        ((float4*)(rawq + i * 36))[f] =
            ((const float4*)(g_q + ((size_t)(b * NN) + i0 + i) * DD))[f];
    }
    {   // Wk[g]: float2 memory layout == pack2(even, odd) -> direct u64 copy
        const u64* wksrc = (const u64*)(Wk + g * DD * DD);
        for (int idx = tid; idx < 512; idx += 384) Wk2[idx] = wksrc[idx];
    }
#pragma unroll
    for (int t = 0; t < 4; ++t) {          // 1536 float4, transpose scatter
        int idx = tid + t * 384;
        int n = idx >> 3, f = idx & 7;
        float4 v4 = ((const float4*)(x + ((size_t)(b * NN) + n) * CC + g * DD))[f];
        vT[(4 * f    ) * 196 + n] = v4.x;
        vT[(4 * f + 1) * 196 + n] = v4.y;
        vT[(4 * f + 2) * 196 + n] = v4.z;
        vT[(4 * f + 3) * 196 + n] = v4.w;
    }
    __syncthreads();

    // ---------------- P0b: qt = rawq * Wk_g -> q_s -----------------------
    // thread: i = tid>>2 (0..95), quarter q4 = tid&3 -> i2-pairs 4q4..4q4+3
    {
        const int iqt = tid >> 2, q4 = tid & 3;
        u64 qacc[4];
#pragma unroll
        for (int p = 0; p < 4; ++p) qacc[p] = 0ull;
        const float* qr = rawq + iqt * 36;
#pragma unroll 8
        for (int o = 0; o < 32; ++o) {
            float qv = qr[o];              // 4-lane broadcast
            u64 qq = pack2(qv, qv);
#pragma unroll
            for (int p = 0; p < 4; ++p)
                ffma2(qacc[p], qq, Wk2[o * 16 + 4 * q4 + p]);
        }
        // write qt pairs into q_s (u64-aligned: 36 floats = 18 u64 stride)
        u64* qdst = (u64*)(q_s + iqt * 36);
#pragma unroll
        for (int p = 0; p < 4; ++p) qdst[4 * q4 + p] = qacc[p];
    }
    __syncthreads();

    // ---------------- P1: S + fused softmax + p write --------------------
    // jq = tid&15 -> j block [12jq, 12jq+12); iq = tid>>4 -> i = iq+24m, m<4
    // No max subtraction: |S_log2| <~ 13, exp2 safe in fp32; softmax is
    // shift-invariant so the result is identical.
    {
        const int jq = tid & 15, iq = tid >> 4;
        u64 acc[24];
#pragma unroll
        for (int t = 0; t < 24; ++t) acc[t] = 0ull;

#pragma unroll 1
        for (int d2 = 0; d2 < 16; ++d2) {
            const int d0 = 2 * d2;
            u64 qp[4];
#pragma unroll
            for (int m = 0; m < 4; ++m)
                qp[m] = *(const u64*)(q_s + (iq + 24 * m) * 36 + d0);  // (d0,d0+1)
            {   // v row d0
                const float4* vr = (const float4*)(vT + d0 * 196);
                u64 vv[6];
#pragma unroll
                for (int c = 0; c < 3; ++c) {
                    float4 v4 = vr[3 * jq + c];
                    vv[2 * c]     = pack2(v4.x, v4.y);
                    vv[2 * c + 1] = pack2(v4.z, v4.w);
                }
#pragma unroll
                for (int m = 0; m < 4; ++m) {
                    float ql, qh; unpack2(qp[m], ql, qh); (void)qh;
                    u64 qa = pack2(ql, ql);
#pragma unroll
                    for (int n = 0; n < 6; ++n)
                        ffma2(acc[m * 6 + n], qa, vv[n]);
                }
            }
            {   // v row d0+1
                const float4* vr = (const float4*)(vT + (d0 + 1) * 196);
                u64 vv[6];
#pragma unroll
                for (int c = 0; c < 3; ++c) {
                    float4 v4 = vr[3 * jq + c];
                    vv[2 * c]     = pack2(v4.x, v4.y);
                    vv[2 * c + 1] = pack2(v4.z, v4.w);
                }
#pragma unroll
                for (int m = 0; m < 4; ++m) {
                    float ql, qh; unpack2(qp[m], ql, qh); (void)ql;
                    u64 qb = pack2(qh, qh);
#pragma unroll
                    for (int n = 0; n < 6; ++n)
                        ffma2(acc[m * 6 + n], qb, vv[n]);
                }
            }
        }

        // ---- fused softmax epilogue (registers + half-warp shfl) ----
        float e[48];
#pragma unroll
        for (int t = 0; t < 24; ++t) {
            float lo, hi; unpack2(acc[t], lo, hi);
            e[2 * t]     = ex2(lo);
            e[2 * t + 1] = ex2(hi);
        }
        float inv[4];
#pragma unroll
        for (int m = 0; m < 4; ++m) {
            float s = 0.f;
#pragma unroll
            for (int jj = 0; jj < 12; ++jj) s += e[m * 12 + jj];
            // 16 lanes sharing iq are a contiguous half-warp covering all j
#pragma unroll
            for (int o = 1; o < 16; o <<= 1)
                s += __shfl_xor_sync(0xffffffffu, s, o);
            inv[m] = 1.0f / s;
        }
        // normalized p to ST (for P3) and attn gmem, straight from registers
#pragma unroll
        for (int m = 0; m < 4; ++m) {
            const int i = iq + 24 * m;
            float4* srow = (float4*)(ST + i * 196);
            float4 p4[3];
#pragma unroll
            for (int c = 0; c < 3; ++c) {
                p4[c] = make_float4(e[m * 12 + 4 * c    ] * inv[m],
                                    e[m * 12 + 4 * c + 1] * inv[m],
                                    e[m * 12 + 4 * c + 2] * inv[m],
                                    e[m * 12 + 4 * c + 3] * inv[m]);
                srow[3 * jq + c] = p4[c];
            }
            if (attn_out) {
                float4* adst = (float4*)(attn_out +
                    ((size_t)bg * NN + i0 + i) * NN + 12 * jq);
#pragma unroll
                for (int c = 0; c < 3; ++c) adst[c] = p4[c];
            }
        }
    }
    __syncthreads();

    // ---------------- P3: ctx[i][d] = sum_j p[i][j] * v[j][d] ------------
    // tq = tid&15 -> d = tq+16dd (dd<2); ig = tid>>4 -> i = 4ig+a (a<4)
    // e-rows broadcast across the 16 lanes sharing ig; float4 over j.
    if (ctx_out) {
        const int tq = tid & 15, ig = tid >> 4;
        u64 acc[8];
#pragma unroll
        for (int t = 0; t < 8; ++t) acc[t] = 0ull;

        const float4* va_row = (const float4*)(vT + tq * 196);
        const float4* vb_row = (const float4*)(vT + (tq + 16) * 196);
#pragma unroll 2
        for (int c = 0; c < 48; ++c) {              // 4 j per step
            float4 v4a = va_row[c], v4b = vb_row[c];
            u64 va0 = pack2(v4a.x, v4a.y), va1 = pack2(v4a.z, v4a.w);
            u64 vb0 = pack2(v4b.x, v4b.y), vb1 = pack2(v4b.z, v4b.w);
#pragma unroll
            for (int a = 0; a < 4; ++a) {
                float4 e4 = ((const float4*)(ST + (4 * ig + a) * 196))[c];  // broadcast
                u64 e0 = pack2(e4.x, e4.y), e1 = pack2(e4.z, e4.w);
                ffma2(acc[a * 2 + 0], e0, va0);
                ffma2(acc[a * 2 + 0], e1, va1);
                ffma2(acc[a * 2 + 1], e0, vb0);
                ffma2(acc[a * 2 + 1], e1, vb1);
            }
        }
#pragma unroll
        for (int a = 0; a < 4; ++a) {
            const size_t row = (size_t)(b * NN) + i0 + 4 * ig + a;
#pragma unroll
            for (int dd = 0; dd < 2; ++dd) {
                float lo, hi; unpack2(acc[a * 2 + dd], lo, hi);
                ctx_out[row * CC + g * DD + tq + 16 * dd] = lo + hi;
            }
        }
    }
}

extern "C" void kernel_launch(void* const* d_in, const int* in_sizes, int n_in,
                              void* d_out, int out_size)
{
    const float* x  = (const float*)d_in[0];
    const float* Wq = (const float*)d_in[1];
    const float* bq = (const float*)d_in[2];
    const float* Wk = (const float*)d_in[3];
    // d_in[4] = bk: provably no effect on outputs (cancels in softmax)

    const size_t ctx_elems  = (size_t)BB * NN * CC;          // 12,582,912
    const size_t attn_elems = (size_t)BB * GG * NN * NN;     // 75,497,472

    float* ctx_ptr  = nullptr;
    float* attn_ptr = nullptr;
    const size_t osz = (size_t)out_size;
    if (osz >= ctx_elems + attn_elems) {          // tuple flattened: ctx then attn
        ctx_ptr  = (float*)d_out;
        attn_ptr = (float*)d_out + ctx_elems;
    } else if (osz == attn_elems) {               // attn only
        attn_ptr = (float*)d_out;
    } else {                                      // ctx only
        ctx_ptr = (float*)d_out;
    }

    constexpr int SMEM_P = 64 * 1024;             // proj: 65536 -> occ 3
    constexpr int SMEM_A = SM_FLOATS * 4;         // attn: 114176 -> occ 2 (24 warps)
    cudaFuncSetAttribute(proj_q_kernel, cudaFuncAttributeMaxDynamicSharedMemorySize, SMEM_P);
    cudaFuncSetAttribute(attn_kernel,   cudaFuncAttributeMaxDynamicSharedMemorySize, SMEM_A);

    proj_q_kernel<<<BB * NN / 32, 128, SMEM_P>>>(x, Wq, bq);
    attn_kernel<<<BB * GG * 2, 384, SMEM_A>>>(x, Wk, ctx_ptr, attn_ptr);
}

// round 14
// speedup vs baseline: 1.4861x; 1.0949x over previous
#include <cuda_runtime.h>

#define BB 256
#define NN 192
#define CC 256
#define GG 8
#define DD 32

// softmax via exp2: fold SCALE * log2(e) into q
#define CSCALE (0.17677669529663688f * 1.4426950408889634f)

typedef unsigned long long u64;

// scratch (allocation-free rule: __device__ global)
// g_q[b][n][o] = CSCALE * (x_n Wq^T + bq)[o]   (6 MB)
__device__ float g_q[BB * NN * DD];

// ---------- packed f32x2 helpers (sm_100+) ----------
__device__ __forceinline__ u64 pack2(float x, float y) {
    u64 r; asm("mov.b64 %0,{%1,%2};" : "=l"(r) : "f"(x), "f"(y)); return r;
}
__device__ __forceinline__ void unpack2(u64 v, float& x, float& y) {
    asm("mov.b64 {%0,%1},%2;" : "=f"(x), "=f"(y) : "l"(v));
}
__device__ __forceinline__ void ffma2(u64& d, u64 a, u64 b) {
    asm("fma.rn.f32x2 %0,%1,%2,%0;" : "+l"(d) : "l"(a), "l"(b));
}
__device__ __forceinline__ float ex2(float x) {
    float r; asm("ex2.approx.ftz.f32 %0,%1;" : "=f"(r) : "f"(x)); return r;
}

// ============================================================
// proj_q: q = (x Wq^T + bq) * CSCALE  (R13 version, measured good).
// 32 rows/block, 128 threads, 64KB smem, occ 3.
// bk is provably irrelevant (constant-in-j logit shift, cancels in softmax).
// ============================================================
__global__ void __launch_bounds__(128, 3) proj_q_kernel(
    const float* __restrict__ x, const float* __restrict__ Wq,
    const float* __restrict__ bq)
{
    extern __shared__ u64 smq[];
    u64* xs2 = smq;            // [32][128] u64 = 32KB
    u64* Wt2 = smq + 4096;     // [128][32] u64 = 32KB

    const int tid = threadIdx.x;
    const int w = tid >> 5, lane = tid & 31;
    const long row0 = (long)blockIdx.x * 32;

    for (int idx = tid; idx < DD * CC; idx += 128) {
        int d = idx >> 8, c = idx & 255;
        ((float*)&Wt2[(c >> 1) * 32 + d])[c & 1] = Wq[idx];
    }
    {
        const float4* src = (const float4*)(x + row0 * CC);
        float4* dst = (float4*)xs2;
#pragma unroll
        for (int t = 0; t < 16; ++t) dst[tid + t * 128] = src[tid + t * 128];
    }
    __syncthreads();

    u64 acc[8];
#pragma unroll
    for (int r = 0; r < 8; ++r) acc[r] = 0ull;
    const u64* xbase = xs2 + (w * 8) * 128;
#pragma unroll 4
    for (int c2 = 0; c2 < 128; ++c2) {
        u64 w2 = Wt2[c2 * 32 + lane];
#pragma unroll
        for (int r = 0; r < 8; ++r)
            ffma2(acc[r], xbase[r * 128 + c2], w2);
    }
    const float bias = bq[lane];
#pragma unroll
    for (int r = 0; r < 8; ++r) {
        float lo, hi; unpack2(acc[r], lo, hi);
        g_q[(row0 + w * 8 + r) * DD + lane] = (lo + hi + bias) * CSCALE;
    }
}

// ============================================================
// attn: R11 structure (measured 295us) + R13's P0b qt-fusion.
// 1 block per (b,g,i-half of 96); 256 threads; 114,176B smem; occ 2.
//   q_s [96][36]  @ 0     (3456 floats)  qt rows (computed in P0b)
//   vT  [32][196] @ 3456  (6272 floats)  x group slice transposed [d][j]
//   ST  [96][196] @ 9728  (18816 floats) P0: rawq[96][36]+Wk2[512]; P1+: p
// P0 : stage rawq (from g_q, 6MB), Wk_g, vT
// P0b: qt[i][i2] = sum_o rawq[i][o] * Wk[g][o][i2] -> q_s
// P1 : S = qt vT (tile 6i x 12j) + fused no-max softmax (half-warp shfl)
//      -> normalized p to ST + attn gmem straight from registers
// P3 : ctx = P V (tile 6i x 2d, e-row broadcast, float4 j-steps)
// ============================================================
#define OFF_VT  3456
#define OFF_ST  9728
#define SM_FLOATS 28544

__global__ void __launch_bounds__(256, 2) attn_kernel(
    const float* __restrict__ x, const float* __restrict__ Wk,
    float* __restrict__ ctx_out, float* __restrict__ attn_out)
{
    extern __shared__ float sm[];
    float* q_s  = sm;
    float* vT   = sm + OFF_VT;
    float* ST   = sm + OFF_ST;
    float* rawq = ST;                     // [96][36], P0 only (dead after P0b)
    u64*   Wk2  = (u64*)(ST + 3456);      // [512] = Wk[g] rows as u64 pairs

    const int tid = threadIdx.x;
    const int bg = blockIdx.x >> 1;        // b*8+g
    const int b = bg >> 3, g = bg & 7;
    const int i0 = (blockIdx.x & 1) * 96;

    // ---------------- P0: stage rawq, Wk2, vT ----------------------------
#pragma unroll
    for (int t = 0; t < 3; ++t) {          // 96 rows x 8 float4 = 768
        int idx = tid + t * 256;
        int i = idx >> 3, f = idx & 7;
        ((float4*)(rawq + i * 36))[f] =
            ((const float4*)(g_q + ((size_t)(b * NN) + i0 + i) * DD))[f];
    }
    {   // Wk[g]: row-major [o][i2]; u64 copy -> Wk2[o*16+p] = (Wk[o][2p], Wk[o][2p+1])
        const u64* wksrc = (const u64*)(Wk + g * DD * DD);
        for (int idx = tid; idx < 512; idx += 256) Wk2[idx] = wksrc[idx];
    }
#pragma unroll
    for (int t = 0; t < 6; ++t) {          // 1536 float4, transpose scatter
        int idx = tid + t * 256;
        int n = idx >> 3, f = idx & 7;
        float4 v4 = ((const float4*)(x + ((size_t)(b * NN) + n) * CC + g * DD))[f];
        vT[(4 * f    ) * 196 + n] = v4.x;
        vT[(4 * f + 1) * 196 + n] = v4.y;
        vT[(4 * f + 2) * 196 + n] = v4.z;
        vT[(4 * f + 3) * 196 + n] = v4.w;
    }
    __syncthreads();

    // ---------------- P0b: qt[i][i2] = sum_o rawq[i][o] * Wk[g][o][i2] ---
    // threads 0..191: iqt = tid>>1 (row), half = tid&1 -> i2-pairs 8h..8h+7
    if (tid < 192) {
        const int iqt = tid >> 1, half = tid & 1;
        u64 qacc[8];
#pragma unroll
        for (int p = 0; p < 8; ++p) qacc[p] = 0ull;
        const float* qr = rawq + iqt * 36;
#pragma unroll 8
        for (int o = 0; o < 32; ++o) {
            float qv = qr[o];              // 2-lane broadcast
            u64 qq = pack2(qv, qv);
            const u64* wrow = Wk2 + o * 16 + 8 * half;
#pragma unroll
            for (int p = 0; p < 8; ++p)
                ffma2(qacc[p], qq, wrow[p]);
        }
        u64* qdst = (u64*)(q_s + iqt * 36);   // 36 floats = 18 u64 stride
#pragma unroll
        for (int p = 0; p < 8; ++p) qdst[8 * half + p] = qacc[p];
    }
    __syncthreads();

    // ---------------- P1: S + fused softmax + p/attn write ---------------
    // jq = tid&15 -> j block [12jq, 12jq+12); iq = tid>>4 -> i = iq+16m, m<6
    // No max subtraction: |S_log2| <~ 13, exp2 safe in fp32; softmax is
    // shift-invariant so the result is identical.
    {
        const int jq = tid & 15, iq = tid >> 4;
        u64 acc[36];
#pragma unroll
        for (int t = 0; t < 36; ++t) acc[t] = 0ull;

#pragma unroll 1
        for (int d2 = 0; d2 < 16; ++d2) {
            const int d0 = 2 * d2;
            u64 qp[6];
#pragma unroll
            for (int m = 0; m < 6; ++m)
                qp[m] = *(const u64*)(q_s + (iq + 16 * m) * 36 + d0);  // (d0,d0+1)
            {   // v row d0
                const float4* vr = (const float4*)(vT + d0 * 196);
                u64 vv[6];
#pragma unroll
                for (int c = 0; c < 3; ++c) {
                    float4 v4 = vr[3 * jq + c];
                    vv[2 * c]     = pack2(v4.x, v4.y);
                    vv[2 * c + 1] = pack2(v4.z, v4.w);
                }
#pragma unroll
                for (int m = 0; m < 6; ++m) {
                    float ql, qh; unpack2(qp[m], ql, qh); (void)qh;
                    u64 qa = pack2(ql, ql);
#pragma unroll
                    for (int n = 0; n < 6; ++n)
                        ffma2(acc[m * 6 + n], qa, vv[n]);
                }
            }
            {   // v row d0+1
                const float4* vr = (const float4*)(vT + (d0 + 1) * 196);
                u64 vv[6];
#pragma unroll
                for (int c = 0; c < 3; ++c) {
                    float4 v4 = vr[3 * jq + c];
                    vv[2 * c]     = pack2(v4.x, v4.y);
                    vv[2 * c + 1] = pack2(v4.z, v4.w);
                }
#pragma unroll
                for (int m = 0; m < 6; ++m) {
                    float ql, qh; unpack2(qp[m], ql, qh); (void)ql;
                    u64 qb = pack2(qh, qh);
#pragma unroll
                    for (int n = 0; n < 6; ++n)
                        ffma2(acc[m * 6 + n], qb, vv[n]);
                }
            }
        }

        // ---- fused softmax epilogue (registers + half-warp shfl) ----
        float e[72];
#pragma unroll
        for (int t = 0; t < 36; ++t) {
            float lo, hi; unpack2(acc[t], lo, hi);
            e[2 * t]     = ex2(lo);
            e[2 * t + 1] = ex2(hi);
        }
        float inv[6];
#pragma unroll
        for (int m = 0; m < 6; ++m) {
            float s = 0.f;
#pragma unroll
            for (int jj = 0; jj < 12; ++jj) s += e[m * 12 + jj];
            // 16 lanes sharing iq are a contiguous half-warp covering all j
#pragma unroll
            for (int o = 1; o < 16; o <<= 1)
                s += __shfl_xor_sync(0xffffffffu, s, o);
            inv[m] = 1.0f / s;
        }
        // normalized p to ST (for P3) and attn gmem, straight from registers
#pragma unroll
        for (int m = 0; m < 6; ++m) {
            const int i = iq + 16 * m;
            float4* srow = (float4*)(ST + i * 196);
            float4 p4[3];
#pragma unroll
            for (int c = 0; c < 3; ++c) {
                p4[c] = make_float4(e[m * 12 + 4 * c    ] * inv[m],
                                    e[m * 12 + 4 * c + 1] * inv[m],
                                    e[m * 12 + 4 * c + 2] * inv[m],
                                    e[m * 12 + 4 * c + 3] * inv[m]);
                srow[3 * jq + c] = p4[c];
            }
            if (attn_out) {
                float4* adst = (float4*)(attn_out +
                    ((size_t)bg * NN + i0 + i) * NN + 12 * jq);
#pragma unroll
                for (int c = 0; c < 3; ++c) adst[c] = p4[c];
            }
        }
    }
    __syncthreads();

    // ---------------- P3: ctx[i][d] = sum_j p[i][j] * v[j][d] ------------
    // tq = tid&15 -> d = tq+16dd (dd<2); ig = tid>>4 -> i = 6ig+a (a<6)
    // e-rows broadcast across the 16 lanes sharing ig; float4 over j.
    if (ctx_out) {
        const int tq = tid & 15, ig = tid >> 4;
        u64 acc[12];
#pragma unroll
        for (int t = 0; t < 12; ++t) acc[t] = 0ull;

        const float4* va_row = (const float4*)(vT + tq * 196);
        const float4* vb_row = (const float4*)(vT + (tq + 16) * 196);
#pragma unroll 2
        for (int c = 0; c < 48; ++c) {              // 4 j per step
            float4 v4a = va_row[c], v4b = vb_row[c];
            u64 va0 = pack2(v4a.x, v4a.y), va1 = pack2(v4a.z, v4a.w);
            u64 vb0 = pack2(v4b.x, v4b.y), vb1 = pack2(v4b.z, v4b.w);
#pragma unroll
            for (int a = 0; a < 6; ++a) {
                float4 e4 = ((const float4*)(ST + (6 * ig + a) * 196))[c];  // broadcast
                u64 e0 = pack2(e4.x, e4.y), e1 = pack2(e4.z, e4.w);
                ffma2(acc[a * 2 + 0], e0, va0);
                ffma2(acc[a * 2 + 0], e1, va1);
                ffma2(acc[a * 2 + 1], e0, vb0);
                ffma2(acc[a * 2 + 1], e1, vb1);
            }
        }
#pragma unroll
        for (int a = 0; a < 6; ++a) {
            const size_t row = (size_t)(b * NN) + i0 + 6 * ig + a;
#pragma unroll
            for (int dd = 0; dd < 2; ++dd) {
                float lo, hi; unpack2(acc[a * 2 + dd], lo, hi);
                ctx_out[row * CC + g * DD + tq + 16 * dd] = lo + hi;
            }
        }
    }
}

extern "C" void kernel_launch(void* const* d_in, const int* in_sizes, int n_in,
                              void* d_out, int out_size)
{
    const float* x  = (const float*)d_in[0];
    const float* Wq = (const float*)d_in[1];
    const float* bq = (const float*)d_in[2];
    const float* Wk = (const float*)d_in[3];
    // d_in[4] = bk: provably no effect on outputs (cancels in softmax)

    const size_t ctx_elems  = (size_t)BB * NN * CC;          // 12,582,912
    const size_t attn_elems = (size_t)BB * GG * NN * NN;     // 75,497,472

    float* ctx_ptr  = nullptr;
    float* attn_ptr = nullptr;
    const size_t osz = (size_t)out_size;
    if (osz >= ctx_elems + attn_elems) {          // tuple flattened: ctx then attn
        ctx_ptr  = (float*)d_out;
        attn_ptr = (float*)d_out + ctx_elems;
    } else if (osz == attn_elems) {               // attn only
        attn_ptr = (float*)d_out;
    } else {                                      // ctx only
        ctx_ptr = (float*)d_out;
    }

    constexpr int SMEM_P = 64 * 1024;             // proj: 65536 -> occ 3
    constexpr int SMEM_A = SM_FLOATS * 4;         // attn: 114176 -> occ 2
    cudaFuncSetAttribute(proj_q_kernel, cudaFuncAttributeMaxDynamicSharedMemorySize, SMEM_P);
    cudaFuncSetAttribute(attn_kernel,   cudaFuncAttributeMaxDynamicSharedMemorySize, SMEM_A);

    proj_q_kernel<<<BB * NN / 32, 128, SMEM_P>>>(x, Wq, bq);
    attn_kernel<<<BB * GG * 2, 256, SMEM_A>>>(x, Wk, ctx_ptr, attn_ptr);
}